// round 15
// baseline (speedup 1.0000x reference)
#include <cuda_runtime.h>
#include <cuda_fp16.h>
#include <cstdint>
#include <cstddef>

#define SDIM 2048
#define BATCH 8
#define NELEM ((size_t)BATCH * SDIM * SDIM)

// Scratch: P then softmax(P). (module-load allocated device global)
__device__ float g_P[NELEM];

#if defined(__CUDA_ARCH_FEAT_SM103_ALL) || defined(__CUDA_ARCH_FEAT_SM100_ALL) || defined(__CUDA_ARCH_FEAT_SM101_ALL)
#define HAS_TC05 1
#else
#define HAS_TC05 0
#endif

__device__ __forceinline__ float to_tf32(float x) {
    float r;
    asm("cvt.rna.tf32.f32 %0, %1;" : "=f"(r) : "f"(x));
    return r;
}
__device__ __forceinline__ uint32_t h2_u32(__half2 h) {
    uint32_t u;
    __half2_raw hr = *reinterpret_cast<__half2_raw*>(&h);
    u = (uint32_t)hr.x | ((uint32_t)hr.y << 16);
    return u;
}
__device__ __forceinline__ uint32_t smem_u32(const void* p) {
    uint32_t a;
    asm("{ .reg .u64 t; cvta.to.shared.u64 t, %1; cvt.u32.u64 %0, t; }" : "=r"(a) : "l"(p));
    return a;
}
__device__ __forceinline__ uint32_t elect_one() {
    uint32_t pred;
    asm volatile("{\n\t.reg .pred p;\n\telect.sync _|p, 0xFFFFFFFF;\n\tselp.b32 %0, 1, 0, p;\n\t}"
                 : "=r"(pred));
    return pred;
}
__device__ __forceinline__ uint32_t swz(uint32_t off) {   // SW128 swizzle
    return off ^ ((off >> 3) & 0x70);
}
__device__ __forceinline__ uint64_t make_desc_sw128(uint32_t addr) {
    const uint64_t base = (uint64_t(2) << 61) | (uint64_t(1) << 46)
                        | (uint64_t(64) << 32) | (uint64_t(1) << 16);
    return base | ((uint64_t)(addr >> 4) & 0x3FFF);
}
__device__ __forceinline__ void mbar_init(uint32_t mbar, uint32_t cnt) {
    asm volatile("mbarrier.init.shared.b64 [%0], %1;" :: "r"(mbar), "r"(cnt) : "memory");
}
__device__ __forceinline__ void mbar_inval(uint32_t mbar) {
    asm volatile("mbarrier.inval.shared.b64 [%0];" :: "r"(mbar) : "memory");
}
__device__ __forceinline__ void mbar_wait(uint32_t mbar, uint32_t phase) {
    asm volatile(
        "{\n\t.reg .pred P;\n\t"
        "WL_%=:\n\t"
        "mbarrier.try_wait.parity.acquire.cta.shared::cta.b64 P, [%0], %1, 0x989680;\n\t"
        "@P bra.uni WD_%=;\n\t"
        "bra.uni WL_%=;\n\t"
        "WD_%=:\n\t}"
        :: "r"(mbar), "r"(phase) : "memory");
}
__device__ __forceinline__ void cp16(uint32_t smem, const void* g) {
    asm volatile("cp.async.cg.shared.global [%0], [%1], 16;" :: "r"(smem), "l"(g));
}
__device__ __forceinline__ void cp_commit() {
    asm volatile("cp.async.commit_group;" ::: "memory");
}
__device__ __forceinline__ void sts128(uint32_t addr, uint32_t a, uint32_t b, uint32_t c, uint32_t d) {
    asm volatile("st.shared.v4.b32 [%0], {%1,%2,%3,%4};"
                 :: "r"(addr), "r"(a), "r"(b), "r"(c), "r"(d) : "memory");
}

#if HAS_TC05
__device__ __forceinline__ void mma_f16_ss(uint32_t d_tmem, uint64_t a_desc, uint64_t b_desc,
                                           uint32_t idesc, uint32_t en) {
    asm volatile(
        "{\n\t.reg .pred p;\n\t"
        "setp.ne.u32 p, %5, 0;\n\t"
        "tcgen05.mma.cta_group::1.kind::f16 [%0], %1, %2, %3, {%4,%4,%4,%4}, p;\n\t}"
        :: "r"(d_tmem), "l"(a_desc), "l"(b_desc), "r"(idesc), "r"(0u), "r"(en)
        : "memory");
}
__device__ __forceinline__ void mma_tf32_ss(uint32_t d_tmem, uint64_t a_desc, uint64_t b_desc,
                                            uint32_t idesc, uint32_t en) {
    asm volatile(
        "{\n\t.reg .pred p;\n\t"
        "setp.ne.u32 p, %5, 0;\n\t"
        "tcgen05.mma.cta_group::1.kind::tf32 [%0], %1, %2, %3, {%4,%4,%4,%4}, p;\n\t}"
        :: "r"(d_tmem), "l"(a_desc), "l"(b_desc), "r"(idesc), "r"(0u), "r"(en)
        : "memory");
}
__device__ __forceinline__ void tc_commit(uint32_t mbar) {
    asm volatile("tcgen05.commit.cta_group::1.mbarrier::arrive::one.shared::cluster.b64 [%0];"
                 :: "r"(mbar) : "memory");
}
__device__ __forceinline__ void tmem_ld32(uint32_t* r, uint32_t taddr) {
    asm volatile(
        "tcgen05.ld.sync.aligned.32x32b.x32.b32 "
        "{%0, %1, %2, %3, %4, %5, %6, %7, "
        " %8, %9, %10, %11, %12, %13, %14, %15, "
        " %16, %17, %18, %19, %20, %21, %22, %23, "
        " %24, %25, %26, %27, %28, %29, %30, %31}, [%32];"
        : "=r"(r[0]),  "=r"(r[1]),  "=r"(r[2]),  "=r"(r[3]),
          "=r"(r[4]),  "=r"(r[5]),  "=r"(r[6]),  "=r"(r[7]),
          "=r"(r[8]),  "=r"(r[9]),  "=r"(r[10]), "=r"(r[11]),
          "=r"(r[12]), "=r"(r[13]), "=r"(r[14]), "=r"(r[15]),
          "=r"(r[16]), "=r"(r[17]), "=r"(r[18]), "=r"(r[19]),
          "=r"(r[20]), "=r"(r[21]), "=r"(r[22]), "=r"(r[23]),
          "=r"(r[24]), "=r"(r[25]), "=r"(r[26]), "=r"(r[27]),
          "=r"(r[28]), "=r"(r[29]), "=r"(r[30]), "=r"(r[31])
        : "r"(taddr));
    asm volatile("tcgen05.wait::ld.sync.aligned;" ::: "memory");
}
#endif

// ===========================================================================
// Pass 1: P = Q @ K^T via f16 2-split tcgen05, split computed IN-LOOP from
// raw fp32 Q,K (no precompute pass). CTA 128x256, BK=64.
//   Dhh (tmem+0)   += Qh.Kh
//   Dx  (tmem+256) += Qh.Kl' + Ql'.Kh     (lo scaled x4096)
//   P = Dhh + Dx/4096
// ===========================================================================
#define G1_NKT   32
#define G1_STAGE 98304           // Ah 16K | Al 16K | Bh 32K | Bl 32K
#define G1_DYN   (2 * G1_STAGE + 1024)
#define G1_IDESC ((1u << 4) | (32u << 17) | (8u << 24))   // F32 acc, f16, N=256, M=128

#if HAS_TC05
// Convert 8 fp32 (two float4) -> 4 half2 hi + 4 half2 lo*4096, store 16B each.
__device__ __forceinline__ void cvt_store8(uint32_t s_hi, uint32_t s_lo,
                                           float4 v0, float4 v1) {
    const __half2 S = __half2half2(__float2half(4096.0f));
    __half2 h0 = __floats2half2_rn(v0.x, v0.y);
    __half2 h1 = __floats2half2_rn(v0.z, v0.w);
    __half2 h2 = __floats2half2_rn(v1.x, v1.y);
    __half2 h3 = __floats2half2_rn(v1.z, v1.w);
    float2 b0 = __half22float2(h0);
    float2 b1 = __half22float2(h1);
    float2 b2 = __half22float2(h2);
    float2 b3 = __half22float2(h3);
    __half2 l0 = __hmul2(__floats2half2_rn(v0.x - b0.x, v0.y - b0.y), S);
    __half2 l1 = __hmul2(__floats2half2_rn(v0.z - b1.x, v0.w - b1.y), S);
    __half2 l2 = __hmul2(__floats2half2_rn(v1.x - b2.x, v1.y - b2.y), S);
    __half2 l3 = __hmul2(__floats2half2_rn(v1.z - b3.x, v1.w - b3.y), S);
    sts128(s_hi, h2_u32(h0), h2_u32(h1), h2_u32(h2), h2_u32(h3));
    sts128(s_lo, h2_u32(l0), h2_u32(l1), h2_u32(l2), h2_u32(l3));
}
#endif

__global__ __launch_bounds__(256, 1)
void gemm1_k(const float* __restrict__ Q, const float* __restrict__ K) {
#if HAS_TC05
    extern __shared__ char dyn[];
    __shared__ __align__(16) uint64_t s_mbar[2];
    __shared__ uint32_t s_tmem[1];

    const uint32_t raw = smem_u32(dyn);
    const uint32_t dbase = (raw + 1023u) & ~1023u;

    const int tid = threadIdx.x;
    const int wid = tid >> 5;
    const int lid = tid & 31;
    const int b   = blockIdx.z;
    const int mt  = blockIdx.y;
    const int nt  = blockIdx.x;
    const size_t bo = (size_t)b * SDIM * SDIM;
    const float* Ag = Q + bo + (size_t)mt * 128 * SDIM;
    const float* Bg = K + bo + (size_t)nt * 256 * SDIM;

    const uint32_t mb0 = smem_u32(&s_mbar[0]);
    const uint32_t mb1 = mb0 + 8;

    if (wid == 0) {
        asm volatile("tcgen05.alloc.cta_group::1.sync.aligned.shared::cta.b32 [%0], %1;"
                     :: "r"(smem_u32(s_tmem)), "r"(512u) : "memory");
    }
    if (tid == 0) { mbar_init(mb0, 1); mbar_init(mb1, 1); }
    __syncthreads();
    const uint32_t tmem = s_tmem[0];

    // 8-float-group maps. A: 1024 groups (128 rows x 8), B: 2048 groups.
    uint32_t aS[4], aG[4], bS[8], bG[8];
    #pragma unroll
    for (int j = 0; j < 4; j++) {
        int g = tid + j * 256;
        aS[j] = swz(((uint32_t)(g >> 3) << 7) | ((uint32_t)(g & 7) << 4));
        aG[j] = (uint32_t)(g >> 3) * SDIM + (uint32_t)(g & 7) * 8;
    }
    #pragma unroll
    for (int j = 0; j < 8; j++) {
        int g = tid + j * 256;
        bS[j] = swz(((uint32_t)(g >> 3) << 7) | ((uint32_t)(g & 7) << 4));
        bG[j] = (uint32_t)(g >> 3) * SDIM + (uint32_t)(g & 7) * 8;
    }

    float4 qa[4][2], kb[8][2];
    // Prefetch kt=0 raw fp32.
    #pragma unroll
    for (int j = 0; j < 4; j++) {
        qa[j][0] = *(const float4*)(Ag + aG[j]);
        qa[j][1] = *(const float4*)(Ag + aG[j] + 4);
    }
    #pragma unroll
    for (int j = 0; j < 8; j++) {
        kb[j][0] = *(const float4*)(Bg + bG[j]);
        kb[j][1] = *(const float4*)(Bg + bG[j] + 4);
    }

    uint32_t ph[2] = {0, 0};

    for (int kt = 0; kt < G1_NKT; kt++) {
        const int s = kt & 1;
        const uint32_t sb = dbase + s * G1_STAGE;

        if (kt >= 2) {
            mbar_wait(s == 0 ? mb0 : mb1, ph[s]);
            ph[s] ^= 1;
        }

        // Convert prefetched regs -> hi/lo f16 tiles in smem.
        #pragma unroll
        for (int j = 0; j < 4; j++)
            cvt_store8(sb + aS[j], sb + 16384 + aS[j], qa[j][0], qa[j][1]);
        #pragma unroll
        for (int j = 0; j < 8; j++)
            cvt_store8(sb + 32768 + bS[j], sb + 65536 + bS[j], kb[j][0], kb[j][1]);

        asm volatile("fence.proxy.async.shared::cta;" ::: "memory");
        __syncthreads();

        if (wid == 0 && elect_one()) {
            const uint64_t dAh = make_desc_sw128(sb);
            const uint64_t dAl = make_desc_sw128(sb + 16384);
            const uint64_t dBh = make_desc_sw128(sb + 32768);
            const uint64_t dBl = make_desc_sw128(sb + 65536);
            #pragma unroll
            for (int ks = 0; ks < 4; ks++) {     // 16 f16 per k-step = 32B
                const uint64_t o = (uint64_t)(ks * 2);
                const uint32_t en = (kt > 0 || ks > 0) ? 1u : 0u;
                mma_f16_ss(tmem,       dAh + o, dBh + o, G1_IDESC, en);
                mma_f16_ss(tmem + 256, dAh + o, dBl + o, G1_IDESC, en);
                mma_f16_ss(tmem + 256, dAl + o, dBh + o, G1_IDESC, 1u);
            }
            tc_commit(s == 0 ? mb0 : mb1);
        }

        // Prefetch next raw fp32 tile (hidden under MMA / L2-bound period).
        if (kt + 1 < G1_NKT) {
            const uint32_t ko = (uint32_t)(kt + 1) * 64;
            #pragma unroll
            for (int j = 0; j < 4; j++) {
                qa[j][0] = *(const float4*)(Ag + aG[j] + ko);
                qa[j][1] = *(const float4*)(Ag + aG[j] + ko + 4);
            }
            #pragma unroll
            for (int j = 0; j < 8; j++) {
                kb[j][0] = *(const float4*)(Bg + bG[j] + ko);
                kb[j][1] = *(const float4*)(Bg + bG[j] + ko + 4);
            }
        }
    }

    mbar_wait(mb0, ph[0]);
    mbar_wait(mb1, ph[1]);
    asm volatile("tcgen05.fence::after_thread_sync;" ::: "memory");

    // Epilogue: warp w -> rows (w&3)*32+lid, cols (w>>2)*128 .. +127.
    {
        const int sub  = wid & 3;
        const int half = wid >> 2;
        const int row  = sub * 32 + lid;
        float* Cb = g_P + bo + ((size_t)mt * 128 + row) * SDIM
                         + (size_t)nt * 256 + (size_t)half * 128;
        const float inv = 1.0f / 4096.0f;
        #pragma unroll
        for (int c0 = 0; c0 < 128; c0 += 32) {
            uint32_t rh[32], rx[32];
            tmem_ld32(rh, tmem + (uint32_t)(half * 128 + c0));
            tmem_ld32(rx, tmem + (uint32_t)(256 + half * 128 + c0));
            #pragma unroll
            for (int j = 0; j < 8; j++) {
                float4 v;
                v.x = __uint_as_float(rh[4*j+0]) + __uint_as_float(rx[4*j+0]) * inv;
                v.y = __uint_as_float(rh[4*j+1]) + __uint_as_float(rx[4*j+1]) * inv;
                v.z = __uint_as_float(rh[4*j+2]) + __uint_as_float(rx[4*j+2]) * inv;
                v.w = __uint_as_float(rh[4*j+3]) + __uint_as_float(rx[4*j+3]) * inv;
                *(float4*)(Cb + c0 + 4*j) = v;
            }
        }
    }

    __syncthreads();
    if (tid == 0) { mbar_inval(mb0); mbar_inval(mb1); }
    __syncthreads();
    if (wid == 0) {
        asm volatile("tcgen05.relinquish_alloc_permit.cta_group::1.sync.aligned;");
        asm volatile("tcgen05.dealloc.cta_group::1.sync.aligned.b32 %0, %1;"
                     :: "r"(tmem), "r"(512u));
    }
#endif
}

// ===========================================================================
// Pass 2: softmax over last dim, in place on g_P.
// ===========================================================================
__global__ __launch_bounds__(256)
void softmax_rows() {
    __shared__ float red[8];
    float* p = g_P + (size_t)blockIdx.x * SDIM;
    const int tid  = threadIdx.x;
    const int lane = tid & 31;
    const int warp = tid >> 5;

    float4 a = *(const float4*)(p + tid * 4);
    float4 b = *(const float4*)(p + 1024 + tid * 4);

    float m = fmaxf(fmaxf(fmaxf(a.x, a.y), fmaxf(a.z, a.w)),
                    fmaxf(fmaxf(b.x, b.y), fmaxf(b.z, b.w)));
    #pragma unroll
    for (int o = 16; o > 0; o >>= 1)
        m = fmaxf(m, __shfl_xor_sync(0xffffffffu, m, o));
    if (lane == 0) red[warp] = m;
    __syncthreads();
    m = red[0];
    #pragma unroll
    for (int i = 1; i < 8; i++) m = fmaxf(m, red[i]);
    __syncthreads();

    a.x = expf(a.x - m); a.y = expf(a.y - m); a.z = expf(a.z - m); a.w = expf(a.w - m);
    b.x = expf(b.x - m); b.y = expf(b.y - m); b.z = expf(b.z - m); b.w = expf(b.w - m);

    float s = (a.x + a.y) + (a.z + a.w) + (b.x + b.y) + (b.z + b.w);
    #pragma unroll
    for (int o = 16; o > 0; o >>= 1)
        s += __shfl_xor_sync(0xffffffffu, s, o);
    if (lane == 0) red[warp] = s;
    __syncthreads();
    s = red[0] + red[1] + red[2] + red[3] + red[4] + red[5] + red[6] + red[7];

    const float r = 1.0f / s;
    a.x *= r; a.y *= r; a.z *= r; a.w *= r;
    b.x *= r; b.y *= r; b.z *= r; b.w *= r;
    *(float4*)(p + tid * 4)        = a;
    *(float4*)(p + 1024 + tid * 4) = b;
}

// ===========================================================================
// Pass 3: out = V @ P via tcgen05 tf32, NT form with B transposed during
// staging (coalesced column gather from g_P; no transpose pass).
// CTA 128x256, BK=32 fp32, 3-stage cp.async for V.
// ===========================================================================
#define G2_NKT   64
#define G2_STAGE 49152           // A 16K | B 32K
#define G2_DYN   (3 * G2_STAGE + 1024)
#define G2_IDESC ((1u << 4) | (2u << 7) | (2u << 10) | (32u << 17) | (8u << 24))

__global__ __launch_bounds__(256, 1)
void gemm2_k(const float* __restrict__ V, float* __restrict__ O) {
#if HAS_TC05
    extern __shared__ char dyn[];
    __shared__ __align__(16) uint64_t s_mbar[3];
    __shared__ uint32_t s_tmem[1];

    const uint32_t raw = smem_u32(dyn);
    const uint32_t dbase = (raw + 1023u) & ~1023u;

    const int tid = threadIdx.x;
    const int wid = tid >> 5;
    const int lid = tid & 31;
    const int b   = blockIdx.z;
    const int mt  = blockIdx.y;
    const int nt  = blockIdx.x;
    const size_t bo = (size_t)b * SDIM * SDIM;
    const float* Ag = V   + bo + (size_t)mt * 128 * SDIM;
    const float* Pg = g_P + bo + (size_t)nt * 256 + tid;   // column n0+tid

    const uint32_t mbb = smem_u32(&s_mbar[0]);

    if (wid == 0) {
        asm volatile("tcgen05.alloc.cta_group::1.sync.aligned.shared::cta.b32 [%0], %1;"
                     :: "r"(smem_u32(s_tmem)), "r"(256u) : "memory");
    }
    if (tid == 0) { mbar_init(mbb, 1); mbar_init(mbb + 8, 1); mbar_init(mbb + 16, 1); }
    __syncthreads();
    const uint32_t tmem = s_tmem[0];

    // A (V): 128 rows x 32 fp32 = 128B rows; 1024 chunks -> 4 cp16/thread.
    uint32_t aS[4], aG[4];
    #pragma unroll
    for (int j = 0; j < 4; j++) {
        int i = tid + j * 256;
        aS[j] = swz(((uint32_t)(i >> 3) << 7) | ((uint32_t)(i & 7) << 4));
        aG[j] = (uint32_t)(i >> 3) * SDIM + (uint32_t)(i & 7) * 4;
    }
    // B: thread owns n-row tid (128B of 32 k-floats). Swizzled 16B chunk addrs:
    uint32_t bS[8];
    #pragma unroll
    for (int c = 0; c < 8; c++)
        bS[c] = swz(((uint32_t)tid << 7) | ((uint32_t)c << 4));

    // Gather B(0): P[k0+k][n0+tid], k = 0..31 (lane-coalesced).
    float bv[32];
    #pragma unroll
    for (int k = 0; k < 32; k++)
        bv[k] = Pg[(size_t)k * SDIM];

    // Prologue: cp.async A for 3 stages.
    #pragma unroll
    for (int p = 0; p < 3; p++) {
        const uint32_t sb = dbase + p * G2_STAGE;
        #pragma unroll
        for (int j = 0; j < 4; j++) cp16(sb + aS[j], Ag + aG[j] + p * 32);
        cp_commit();
    }

    uint32_t ph[3] = {0, 0, 0};
    int s = 0;

    for (int kt = 0; kt < G2_NKT; kt++) {
        const uint32_t sb = dbase + s * G2_STAGE;

        if      (kt >= G2_NKT - 1) asm volatile("cp.async.wait_group 0;" ::: "memory");
        else if (kt == G2_NKT - 2) asm volatile("cp.async.wait_group 1;" ::: "memory");
        else                       asm volatile("cp.async.wait_group 2;" ::: "memory");

        // STS B(kt) from gathered regs (tf32-rounded).
        #pragma unroll
        for (int c = 0; c < 8; c++) {
            sts128(sb + 16384 + bS[c],
                   __float_as_uint(to_tf32(bv[4*c+0])),
                   __float_as_uint(to_tf32(bv[4*c+1])),
                   __float_as_uint(to_tf32(bv[4*c+2])),
                   __float_as_uint(to_tf32(bv[4*c+3])));
        }

        asm volatile("fence.proxy.async.shared::cta;" ::: "memory");
        __syncthreads();

        if (wid == 0 && elect_one()) {
            const uint64_t dA = make_desc_sw128(sb);
            const uint64_t dB = make_desc_sw128(sb + 16384);
            #pragma unroll
            for (int ks = 0; ks < 4; ks++) {   // 8 tf32 per k-step = 32B
                const uint64_t o = (uint64_t)(ks * 2);
                mma_tf32_ss(tmem, dA + o, dB + o, G2_IDESC, (kt > 0 || ks > 0) ? 1u : 0u);
            }
            tc_commit(mbb + 8 * s);
        }

        // Gather B(kt+1) (overlaps MMA completion wait below).
        if (kt + 1 < G2_NKT) {
            const size_t ko = (size_t)(kt + 1) * 32;
            #pragma unroll
            for (int k = 0; k < 32; k++)
                bv[k] = Pg[(ko + k) * SDIM];
        }

        // Refill A for kt+3 once this stage's MMA is done.
        if (kt + 3 < G2_NKT) {
            mbar_wait(mbb + 8 * s, ph[s]);
            ph[s] ^= 1;
            const uint32_t ko = (uint32_t)(kt + 3) * 32;
            #pragma unroll
            for (int j = 0; j < 4; j++) cp16(sb + aS[j], Ag + aG[j] + ko);
            cp_commit();
        }
        s = (s == 2) ? 0 : s + 1;
    }

    mbar_wait(mbb,      ph[0]);
    mbar_wait(mbb + 8,  ph[1]);
    mbar_wait(mbb + 16, ph[2]);
    asm volatile("tcgen05.fence::after_thread_sync;" ::: "memory");

    {
        const int sub  = wid & 3;
        const int half = wid >> 2;
        const int row  = sub * 32 + lid;
        float* Ob = O + bo + ((size_t)mt * 128 + row) * SDIM
                       + (size_t)nt * 256 + (size_t)half * 128;
        #pragma unroll
        for (int c0 = 0; c0 < 128; c0 += 32) {
            uint32_t r[32];
            tmem_ld32(r, tmem + (uint32_t)(half * 128 + c0));
            #pragma unroll
            for (int j = 0; j < 8; j++) {
                float4 v;
                v.x = __uint_as_float(r[4*j+0]);
                v.y = __uint_as_float(r[4*j+1]);
                v.z = __uint_as_float(r[4*j+2]);
                v.w = __uint_as_float(r[4*j+3]);
                *(float4*)(Ob + c0 + 4*j) = v;
            }
        }
    }

    __syncthreads();
    if (tid == 0) { mbar_inval(mbb); mbar_inval(mbb + 8); mbar_inval(mbb + 16); }
    __syncthreads();
    if (wid == 0) {
        asm volatile("tcgen05.relinquish_alloc_permit.cta_group::1.sync.aligned;");
        asm volatile("tcgen05.dealloc.cta_group::1.sync.aligned.b32 %0, %1;"
                     :: "r"(tmem), "r"(256u));
    }
#endif
}

// ===========================================================================
extern "C" void kernel_launch(void* const* d_in, const int* in_sizes, int n_in,
                              void* d_out, int out_size) {
    (void)in_sizes; (void)n_in; (void)out_size;
    const float* Q = (const float*)d_in[0];
    const float* K = (const float*)d_in[1];
    const float* V = (const float*)d_in[2];
    float* O = (float*)d_out;

    cudaFuncSetAttribute((const void*)gemm1_k,
                         cudaFuncAttributeMaxDynamicSharedMemorySize, G1_DYN);
    cudaFuncSetAttribute((const void*)gemm2_k,
                         cudaFuncAttributeMaxDynamicSharedMemorySize, G2_DYN);

    gemm1_k<<<dim3(SDIM / 256, SDIM / 128, BATCH), 256, G1_DYN>>>(Q, K);
    softmax_rows<<<BATCH * SDIM, 256>>>();
    gemm2_k<<<dim3(SDIM / 256, SDIM / 128, BATCH), 256, G2_DYN>>>(V, O);
}

// round 17
// speedup vs baseline: 1.3135x; 1.3135x over previous
#include <cuda_runtime.h>
#include <cuda_fp16.h>
#include <cstdint>
#include <cstddef>

#define SDIM 2048
#define BATCH 8
#define NELEM ((size_t)BATCH * SDIM * SDIM)

// Device-global scratch (module-load allocated; no runtime allocation).
__device__ float g_P[NELEM];                         // logits, then softmax(P)
__device__ __align__(16) __half g_Pth[NELEM];        // softmax(P)^T as f16
__device__ __align__(16) __half g_Qh16[NELEM];
__device__ __align__(16) __half g_Ql16[NELEM];       // (q - qh) * 4096
__device__ __align__(16) __half g_Kh16[NELEM];
__device__ __align__(16) __half g_Kl16[NELEM];
__device__ __align__(16) __half g_Vh16[NELEM];
__device__ __align__(16) __half g_Vl16[NELEM];       // (v - vh) * 4096

#if defined(__CUDA_ARCH_FEAT_SM103_ALL) || defined(__CUDA_ARCH_FEAT_SM100_ALL) || defined(__CUDA_ARCH_FEAT_SM101_ALL)
#define HAS_TC05 1
#else
#define HAS_TC05 0
#endif

__device__ __forceinline__ uint32_t smem_u32(const void* p) {
    uint32_t a;
    asm("{ .reg .u64 t; cvta.to.shared.u64 t, %1; cvt.u32.u64 %0, t; }" : "=r"(a) : "l"(p));
    return a;
}
__device__ __forceinline__ uint32_t elect_one() {
    uint32_t pred;
    asm volatile("{\n\t.reg .pred p;\n\telect.sync _|p, 0xFFFFFFFF;\n\tselp.b32 %0, 1, 0, p;\n\t}"
                 : "=r"(pred));
    return pred;
}
__device__ __forceinline__ uint32_t swz(uint32_t off) {   // SW128 swizzle
    return off ^ ((off >> 3) & 0x70);
}
__device__ __forceinline__ uint64_t make_desc_sw128(uint32_t addr) {
    const uint64_t base = (uint64_t(2) << 61) | (uint64_t(1) << 46)
                        | (uint64_t(64) << 32) | (uint64_t(1) << 16);
    return base | ((uint64_t)(addr >> 4) & 0x3FFF);
}
__device__ __forceinline__ void mbar_init(uint32_t mbar, uint32_t cnt) {
    asm volatile("mbarrier.init.shared.b64 [%0], %1;" :: "r"(mbar), "r"(cnt) : "memory");
}
__device__ __forceinline__ void mbar_inval(uint32_t mbar) {
    asm volatile("mbarrier.inval.shared.b64 [%0];" :: "r"(mbar) : "memory");
}
__device__ __forceinline__ void mbar_wait(uint32_t mbar, uint32_t phase) {
    asm volatile(
        "{\n\t.reg .pred P;\n\t"
        "WL_%=:\n\t"
        "mbarrier.try_wait.parity.acquire.cta.shared::cta.b64 P, [%0], %1, 0x989680;\n\t"
        "@P bra.uni WD_%=;\n\t"
        "bra.uni WL_%=;\n\t"
        "WD_%=:\n\t}"
        :: "r"(mbar), "r"(phase) : "memory");
}
__device__ __forceinline__ void cp16(uint32_t smem, const void* g) {
    asm volatile("cp.async.cg.shared.global [%0], [%1], 16;" :: "r"(smem), "l"(g));
}
__device__ __forceinline__ void cp_commit() {
    asm volatile("cp.async.commit_group;" ::: "memory");
}

#if HAS_TC05
__device__ __forceinline__ void mma_f16_ss(uint32_t d_tmem, uint64_t a_desc, uint64_t b_desc,
                                           uint32_t idesc, uint32_t en) {
    asm volatile(
        "{\n\t.reg .pred p;\n\t"
        "setp.ne.u32 p, %5, 0;\n\t"
        "tcgen05.mma.cta_group::1.kind::f16 [%0], %1, %2, %3, {%4,%4,%4,%4}, p;\n\t}"
        :: "r"(d_tmem), "l"(a_desc), "l"(b_desc), "r"(idesc), "r"(0u), "r"(en)
        : "memory");
}
__device__ __forceinline__ void tc_commit(uint32_t mbar) {
    asm volatile("tcgen05.commit.cta_group::1.mbarrier::arrive::one.shared::cluster.b64 [%0];"
                 :: "r"(mbar) : "memory");
}
__device__ __forceinline__ void tmem_ld32(uint32_t* r, uint32_t taddr) {
    asm volatile(
        "tcgen05.ld.sync.aligned.32x32b.x32.b32 "
        "{%0, %1, %2, %3, %4, %5, %6, %7, "
        " %8, %9, %10, %11, %12, %13, %14, %15, "
        " %16, %17, %18, %19, %20, %21, %22, %23, "
        " %24, %25, %26, %27, %28, %29, %30, %31}, [%32];"
        : "=r"(r[0]),  "=r"(r[1]),  "=r"(r[2]),  "=r"(r[3]),
          "=r"(r[4]),  "=r"(r[5]),  "=r"(r[6]),  "=r"(r[7]),
          "=r"(r[8]),  "=r"(r[9]),  "=r"(r[10]), "=r"(r[11]),
          "=r"(r[12]), "=r"(r[13]), "=r"(r[14]), "=r"(r[15]),
          "=r"(r[16]), "=r"(r[17]), "=r"(r[18]), "=r"(r[19]),
          "=r"(r[20]), "=r"(r[21]), "=r"(r[22]), "=r"(r[23]),
          "=r"(r[24]), "=r"(r[25]), "=r"(r[26]), "=r"(r[27]),
          "=r"(r[28]), "=r"(r[29]), "=r"(r[30]), "=r"(r[31])
        : "r"(taddr));
    asm volatile("tcgen05.wait::ld.sync.aligned;" ::: "memory");
}
#endif

// F32 acc, f16 a/b, N=256, M=128
#define IDESC_F16 ((1u << 4) | (32u << 17) | (8u << 24))

// ===========================================================================
// Pass 0: split Q,K,V into f16 hi + scaled-lo arrays.
// ===========================================================================
__global__ __launch_bounds__(256)
void split16(const float* __restrict__ Q, const float* __restrict__ K,
             const float* __restrict__ V) {
    size_t i = (size_t)blockIdx.x * 256 + threadIdx.x;   // float4 index
    #pragma unroll
    for (int t = 0; t < 3; t++) {
        const float* src = (t == 0) ? Q : (t == 1) ? K : V;
        __half* dh = (t == 0) ? g_Qh16 : (t == 1) ? g_Kh16 : g_Vh16;
        __half* dl = (t == 0) ? g_Ql16 : (t == 1) ? g_Kl16 : g_Vl16;
        float4 v = ((const float4*)src)[i];
        __half h0 = __float2half_rn(v.x), h1 = __float2half_rn(v.y);
        __half h2 = __float2half_rn(v.z), h3 = __float2half_rn(v.w);
        __half l0 = __float2half_rn((v.x - __half2float(h0)) * 4096.f);
        __half l1 = __float2half_rn((v.y - __half2float(h1)) * 4096.f);
        __half l2 = __float2half_rn((v.z - __half2float(h2)) * 4096.f);
        __half l3 = __float2half_rn((v.w - __half2float(h3)) * 4096.f);
        ((__half2*)dh)[i*2]   = __halves2half2(h0, h1);
        ((__half2*)dh)[i*2+1] = __halves2half2(h2, h3);
        ((__half2*)dl)[i*2]   = __halves2half2(l0, l1);
        ((__half2*)dl)[i*2+1] = __halves2half2(l2, l3);
    }
}

// ===========================================================================
// Pass 1: P = Q @ K^T via f16 2-split tcgen05 (round-11 proven version).
// CTA 128x256, BK=64 f16, 2-stage cp.async.
//   Dhh (tmem+0) += Qh.Kh ; Dx (tmem+256) += Qh.Kl' + Ql'.Kh ; P = Dhh + Dx/4096
// ===========================================================================
#define G1_NKT   32
#define G1_STAGE 98304           // Ah 16K | Al 16K | Bh 32K | Bl 32K
#define G1_DYN   (2 * G1_STAGE + 1024)

__global__ __launch_bounds__(256, 1)
void gemm1_k() {
#if HAS_TC05
    extern __shared__ char dyn[];
    __shared__ __align__(16) uint64_t s_mbar[2];
    __shared__ uint32_t s_tmem[1];

    const uint32_t raw = smem_u32(dyn);
    const uint32_t dbase = (raw + 1023u) & ~1023u;

    const int tid = threadIdx.x;
    const int wid = tid >> 5;
    const int lid = tid & 31;
    const int b   = blockIdx.z;
    const int mt  = blockIdx.y;
    const int nt  = blockIdx.x;
    const size_t bo = (size_t)b * SDIM * SDIM;
    const __half* Ah_g = g_Qh16 + bo + (size_t)mt * 128 * SDIM;
    const __half* Al_g = g_Ql16 + bo + (size_t)mt * 128 * SDIM;
    const __half* Bh_g = g_Kh16 + bo + (size_t)nt * 256 * SDIM;
    const __half* Bl_g = g_Kl16 + bo + (size_t)nt * 256 * SDIM;

    const uint32_t mb0 = smem_u32(&s_mbar[0]);
    const uint32_t mb1 = mb0 + 8;

    if (wid == 0) {
        asm volatile("tcgen05.alloc.cta_group::1.sync.aligned.shared::cta.b32 [%0], %1;"
                     :: "r"(smem_u32(s_tmem)), "r"(512u) : "memory");
    }
    if (tid == 0) { mbar_init(mb0, 1); mbar_init(mb1, 1); }
    __syncthreads();
    const uint32_t tmem = s_tmem[0];

    uint32_t soffA[4], goffA[4], soffB[8], goffB[8];
    #pragma unroll
    for (int j = 0; j < 4; j++) {
        int i = tid + j * 256;
        soffA[j] = swz(((uint32_t)(i >> 3) << 7) | ((uint32_t)(i & 7) << 4));
        goffA[j] = (uint32_t)(i >> 3) * SDIM + (uint32_t)(i & 7) * 8;
    }
    #pragma unroll
    for (int j = 0; j < 8; j++) {
        int i = tid + j * 256;
        soffB[j] = swz(((uint32_t)(i >> 3) << 7) | ((uint32_t)(i & 7) << 4));
        goffB[j] = (uint32_t)(i >> 3) * SDIM + (uint32_t)(i & 7) * 8;
    }

    #pragma unroll
    for (int p = 0; p < 2; p++) {
        const uint32_t sb = dbase + p * G1_STAGE;
        const uint32_t ko = p * 64;
        #pragma unroll
        for (int j = 0; j < 4; j++) {
            cp16(sb +         soffA[j], Ah_g + goffA[j] + ko);
            cp16(sb + 16384 + soffA[j], Al_g + goffA[j] + ko);
        }
        #pragma unroll
        for (int j = 0; j < 8; j++) {
            cp16(sb + 32768 + soffB[j], Bh_g + goffB[j] + ko);
            cp16(sb + 65536 + soffB[j], Bl_g + goffB[j] + ko);
        }
        cp_commit();
    }

    uint32_t ph[2] = {0, 0};

    for (int kt = 0; kt < G1_NKT; kt++) {
        const int s = kt & 1;
        const uint32_t sb = dbase + s * G1_STAGE;

        if (kt == G1_NKT - 1) asm volatile("cp.async.wait_group 0;" ::: "memory");
        else                  asm volatile("cp.async.wait_group 1;" ::: "memory");
        asm volatile("fence.proxy.async.shared::cta;" ::: "memory");
        __syncthreads();

        if (wid == 0 && elect_one()) {
            const uint64_t dAh = make_desc_sw128(sb);
            const uint64_t dAl = make_desc_sw128(sb + 16384);
            const uint64_t dBh = make_desc_sw128(sb + 32768);
            const uint64_t dBl = make_desc_sw128(sb + 65536);
            #pragma unroll
            for (int ks = 0; ks < 4; ks++) {       // 16 f16 per k-step = 32B
                const uint64_t o = (uint64_t)(ks * 2);
                const uint32_t en = (kt > 0 || ks > 0) ? 1u : 0u;
                mma_f16_ss(tmem,       dAh + o, dBh + o, IDESC_F16, en);
                mma_f16_ss(tmem + 256, dAh + o, dBl + o, IDESC_F16, en);
                mma_f16_ss(tmem + 256, dAl + o, dBh + o, IDESC_F16, 1u);
            }
            tc_commit(s == 0 ? mb0 : mb1);
        }

        if (kt + 2 < G1_NKT) {                    // refill this stage
            mbar_wait(s == 0 ? mb0 : mb1, ph[s]);
            ph[s] ^= 1;
            const uint32_t ko = (uint32_t)(kt + 2) * 64;
            #pragma unroll
            for (int j = 0; j < 4; j++) {
                cp16(sb +         soffA[j], Ah_g + goffA[j] + ko);
                cp16(sb + 16384 + soffA[j], Al_g + goffA[j] + ko);
            }
            #pragma unroll
            for (int j = 0; j < 8; j++) {
                cp16(sb + 32768 + soffB[j], Bh_g + goffB[j] + ko);
                cp16(sb + 65536 + soffB[j], Bl_g + goffB[j] + ko);
            }
            cp_commit();
        }
    }

    mbar_wait(mb0, ph[0]);
    mbar_wait(mb1, ph[1]);
    asm volatile("tcgen05.fence::after_thread_sync;" ::: "memory");

    {
        const int sub  = wid & 3;
        const int half = wid >> 2;
        const int row  = sub * 32 + lid;
        float* Cb = g_P + bo + ((size_t)mt * 128 + row) * SDIM
                         + (size_t)nt * 256 + (size_t)half * 128;
        const float inv = 1.0f / 4096.0f;
        #pragma unroll
        for (int c0 = 0; c0 < 128; c0 += 32) {
            uint32_t rh[32], rx[32];
            tmem_ld32(rh, tmem + (uint32_t)(half * 128 + c0));
            tmem_ld32(rx, tmem + (uint32_t)(256 + half * 128 + c0));
            #pragma unroll
            for (int j = 0; j < 8; j++) {
                float4 v;
                v.x = __uint_as_float(rh[4*j+0]) + __uint_as_float(rx[4*j+0]) * inv;
                v.y = __uint_as_float(rh[4*j+1]) + __uint_as_float(rx[4*j+1]) * inv;
                v.z = __uint_as_float(rh[4*j+2]) + __uint_as_float(rx[4*j+2]) * inv;
                v.w = __uint_as_float(rh[4*j+3]) + __uint_as_float(rx[4*j+3]) * inv;
                *(float4*)(Cb + c0 + 4*j) = v;
            }
        }
    }

    __syncthreads();
    if (tid == 0) { mbar_inval(mb0); mbar_inval(mb1); }
    __syncthreads();
    if (wid == 0) {
        asm volatile("tcgen05.relinquish_alloc_permit.cta_group::1.sync.aligned;");
        asm volatile("tcgen05.dealloc.cta_group::1.sync.aligned.b32 %0, %1;"
                     :: "r"(tmem), "r"(512u));
    }
#endif
}

// ===========================================================================
// Pass 2: softmax over last dim, in place on g_P.
// ===========================================================================
__global__ __launch_bounds__(256)
void softmax_rows() {
    __shared__ float red[8];
    float* p = g_P + (size_t)blockIdx.x * SDIM;
    const int tid  = threadIdx.x;
    const int lane = tid & 31;
    const int warp = tid >> 5;

    float4 a = *(const float4*)(p + tid * 4);
    float4 b = *(const float4*)(p + 1024 + tid * 4);

    float m = fmaxf(fmaxf(fmaxf(a.x, a.y), fmaxf(a.z, a.w)),
                    fmaxf(fmaxf(b.x, b.y), fmaxf(b.z, b.w)));
    #pragma unroll
    for (int o = 16; o > 0; o >>= 1)
        m = fmaxf(m, __shfl_xor_sync(0xffffffffu, m, o));
    if (lane == 0) red[warp] = m;
    __syncthreads();
    m = red[0];
    #pragma unroll
    for (int i = 1; i < 8; i++) m = fmaxf(m, red[i]);
    __syncthreads();

    a.x = expf(a.x - m); a.y = expf(a.y - m); a.z = expf(a.z - m); a.w = expf(a.w - m);
    b.x = expf(b.x - m); b.y = expf(b.y - m); b.z = expf(b.z - m); b.w = expf(b.w - m);

    float s = (a.x + a.y) + (a.z + a.w) + (b.x + b.y) + (b.z + b.w);
    #pragma unroll
    for (int o = 16; o > 0; o >>= 1)
        s += __shfl_xor_sync(0xffffffffu, s, o);
    if (lane == 0) red[warp] = s;
    __syncthreads();
    s = red[0] + red[1] + red[2] + red[3] + red[4] + red[5] + red[6] + red[7];

    const float r = 1.0f / s;
    a.x *= r; a.y *= r; a.z *= r; a.w *= r;
    b.x *= r; b.y *= r; b.z *= r; b.w *= r;
    *(float4*)(p + tid * 4)        = a;
    *(float4*)(p + 1024 + tid * 4) = b;
}

// ===========================================================================
// Pass 3: Pth[b][k][d] = f16(P[b][d][k])  (32x32 smem tile transpose, f16 out)
// ===========================================================================
__global__ __launch_bounds__(256)
void transpose_p() {
    __shared__ float t[32][33];
    const int b  = blockIdx.z;
    const int d0 = blockIdx.y * 32;
    const int k0 = blockIdx.x * 32;
    const int x  = threadIdx.x;        // 0..31
    const int y  = threadIdx.y;        // 0..7
    const size_t bo = (size_t)b * SDIM * SDIM;

    #pragma unroll
    for (int j = 0; j < 4; j++)
        t[y + 8*j][x] = g_P[bo + (size_t)(d0 + y + 8*j) * SDIM + k0 + x];
    __syncthreads();
    #pragma unroll
    for (int j = 0; j < 4; j++)
        g_Pth[bo + (size_t)(k0 + y + 8*j) * SDIM + d0 + x] = __float2half_rn(t[x][y + 8*j]);
}

// ===========================================================================
// Pass 4: out = V @ P via f16 2-split tcgen05 (V = Vh + Vl/4096, B = Pth).
// CTA 128x256, BK=64 f16, 2-stage cp.async.
//   Dhh (tmem+0) += Vh.B ; Dx (tmem+256) += Vl'.B ; O = Dhh + Dx/4096
// ===========================================================================
#define G2_NKT   32
#define G2_STAGE 65536           // Ah 16K | Al 16K | B 32K
#define G2_DYN   (2 * G2_STAGE + 1024)

__global__ __launch_bounds__(256, 1)
void gemm2_k(float* __restrict__ O) {
#if HAS_TC05
    extern __shared__ char dyn[];
    __shared__ __align__(16) uint64_t s_mbar[2];
    __shared__ uint32_t s_tmem[1];

    const uint32_t raw = smem_u32(dyn);
    const uint32_t dbase = (raw + 1023u) & ~1023u;

    const int tid = threadIdx.x;
    const int wid = tid >> 5;
    const int lid = tid & 31;
    const int b   = blockIdx.z;
    const int mt  = blockIdx.y;
    const int nt  = blockIdx.x;
    const size_t bo = (size_t)b * SDIM * SDIM;
    const __half* Ah_g = g_Vh16 + bo + (size_t)mt * 128 * SDIM;
    const __half* Al_g = g_Vl16 + bo + (size_t)mt * 128 * SDIM;
    const __half* B_g  = g_Pth  + bo + (size_t)nt * 256 * SDIM;

    const uint32_t mb0 = smem_u32(&s_mbar[0]);
    const uint32_t mb1 = mb0 + 8;

    if (wid == 0) {
        asm volatile("tcgen05.alloc.cta_group::1.sync.aligned.shared::cta.b32 [%0], %1;"
                     :: "r"(smem_u32(s_tmem)), "r"(512u) : "memory");
    }
    if (tid == 0) { mbar_init(mb0, 1); mbar_init(mb1, 1); }
    __syncthreads();
    const uint32_t tmem = s_tmem[0];

    uint32_t soffA[4], goffA[4], soffB[8], goffB[8];
    #pragma unroll
    for (int j = 0; j < 4; j++) {
        int i = tid + j * 256;
        soffA[j] = swz(((uint32_t)(i >> 3) << 7) | ((uint32_t)(i & 7) << 4));
        goffA[j] = (uint32_t)(i >> 3) * SDIM + (uint32_t)(i & 7) * 8;
    }
    #pragma unroll
    for (int j = 0; j < 8; j++) {
        int i = tid + j * 256;
        soffB[j] = swz(((uint32_t)(i >> 3) << 7) | ((uint32_t)(i & 7) << 4));
        goffB[j] = (uint32_t)(i >> 3) * SDIM + (uint32_t)(i & 7) * 8;
    }

    #pragma unroll
    for (int p = 0; p < 2; p++) {
        const uint32_t sb = dbase + p * G2_STAGE;
        const uint32_t ko = p * 64;
        #pragma unroll
        for (int j = 0; j < 4; j++) {
            cp16(sb +         soffA[j], Ah_g + goffA[j] + ko);
            cp16(sb + 16384 + soffA[j], Al_g + goffA[j] + ko);
        }
        #pragma unroll
        for (int j = 0; j < 8; j++)
            cp16(sb + 32768 + soffB[j], B_g + goffB[j] + ko);
        cp_commit();
    }

    uint32_t ph[2] = {0, 0};

    for (int kt = 0; kt < G2_NKT; kt++) {
        const int s = kt & 1;
        const uint32_t sb = dbase + s * G2_STAGE;

        if (kt == G2_NKT - 1) asm volatile("cp.async.wait_group 0;" ::: "memory");
        else                  asm volatile("cp.async.wait_group 1;" ::: "memory");
        asm volatile("fence.proxy.async.shared::cta;" ::: "memory");
        __syncthreads();

        if (wid == 0 && elect_one()) {
            const uint64_t dAh = make_desc_sw128(sb);
            const uint64_t dAl = make_desc_sw128(sb + 16384);
            const uint64_t dB  = make_desc_sw128(sb + 32768);
            #pragma unroll
            for (int ks = 0; ks < 4; ks++) {
                const uint64_t o = (uint64_t)(ks * 2);
                const uint32_t en = (kt > 0 || ks > 0) ? 1u : 0u;
                mma_f16_ss(tmem,       dAh + o, dB + o, IDESC_F16, en);
                mma_f16_ss(tmem + 256, dAl + o, dB + o, IDESC_F16, en);
            }
            tc_commit(s == 0 ? mb0 : mb1);
        }

        if (kt + 2 < G2_NKT) {
            mbar_wait(s == 0 ? mb0 : mb1, ph[s]);
            ph[s] ^= 1;
            const uint32_t ko = (uint32_t)(kt + 2) * 64;
            #pragma unroll
            for (int j = 0; j < 4; j++) {
                cp16(sb +         soffA[j], Ah_g + goffA[j] + ko);
                cp16(sb + 16384 + soffA[j], Al_g + goffA[j] + ko);
            }
            #pragma unroll
            for (int j = 0; j < 8; j++)
                cp16(sb + 32768 + soffB[j], B_g + goffB[j] + ko);
            cp_commit();
        }
    }

    mbar_wait(mb0, ph[0]);
    mbar_wait(mb1, ph[1]);
    asm volatile("tcgen05.fence::after_thread_sync;" ::: "memory");

    {
        const int sub  = wid & 3;
        const int half = wid >> 2;
        const int row  = sub * 32 + lid;
        float* Ob = O + bo + ((size_t)mt * 128 + row) * SDIM
                       + (size_t)nt * 256 + (size_t)half * 128;
        const float inv = 1.0f / 4096.0f;
        #pragma unroll
        for (int c0 = 0; c0 < 128; c0 += 32) {
            uint32_t rh[32], rx[32];
            tmem_ld32(rh, tmem + (uint32_t)(half * 128 + c0));
            tmem_ld32(rx, tmem + (uint32_t)(256 + half * 128 + c0));
            #pragma unroll
            for (int j = 0; j < 8; j++) {
                float4 v;
                v.x = __uint_as_float(rh[4*j+0]) + __uint_as_float(rx[4*j+0]) * inv;
                v.y = __uint_as_float(rh[4*j+1]) + __uint_as_float(rx[4*j+1]) * inv;
                v.z = __uint_as_float(rh[4*j+2]) + __uint_as_float(rx[4*j+2]) * inv;
                v.w = __uint_as_float(rh[4*j+3]) + __uint_as_float(rx[4*j+3]) * inv;
                *(float4*)(Ob + c0 + 4*j) = v;
            }
        }
    }

    __syncthreads();
    if (tid == 0) { mbar_inval(mb0); mbar_inval(mb1); }
    __syncthreads();
    if (wid == 0) {
        asm volatile("tcgen05.relinquish_alloc_permit.cta_group::1.sync.aligned;");
        asm volatile("tcgen05.dealloc.cta_group::1.sync.aligned.b32 %0, %1;"
                     :: "r"(tmem), "r"(512u));
    }
#endif
}

// ===========================================================================
extern "C" void kernel_launch(void* const* d_in, const int* in_sizes, int n_in,
                              void* d_out, int out_size) {
    (void)in_sizes; (void)n_in; (void)out_size;
    const float* Q = (const float*)d_in[0];
    const float* K = (const float*)d_in[1];
    const float* V = (const float*)d_in[2];
    float* O = (float*)d_out;

    cudaFuncSetAttribute((const void*)gemm1_k,
                         cudaFuncAttributeMaxDynamicSharedMemorySize, G1_DYN);
    cudaFuncSetAttribute((const void*)gemm2_k,
                         cudaFuncAttributeMaxDynamicSharedMemorySize, G2_DYN);

    split16<<<(unsigned)(NELEM / 4 / 256), 256>>>(Q, K, V);
    gemm1_k<<<dim3(SDIM / 256, SDIM / 128, BATCH), 256, G1_DYN>>>();
    softmax_rows<<<BATCH * SDIM, 256>>>();
    transpose_p<<<dim3(SDIM / 32, SDIM / 32, BATCH), dim3(32, 8)>>>();
    gemm2_k<<<dim3(SDIM / 256, SDIM / 128, BATCH), 256, G2_DYN>>>(O);
}